// round 1
// baseline (speedup 1.0000x reference)
#include <cuda_runtime.h>
#include <math.h>

#define B_  4
#define T_  2048
#define E_  1024
#define H_  16
#define HD_ 64
#define M_  (B_*T_)   // 8192

// Scratch (device globals: allocation-free)
__device__ float g_q[M_*E_];
__device__ float g_k[M_*E_];
__device__ float g_v[M_*E_];
__device__ float g_y[M_*E_];

// ---------------------------------------------------------------------------
// SGEMM: C[M,N] = A[M,K] @ W[K,N] + bias, M=8192, N=K=1024.
// 128x128 tile, BK=8, 256 threads, 8x8 per thread.
// REORDER=true writes C in [B,H,T,hd] layout (for Q/K/V).
// ---------------------------------------------------------------------------
template<bool REORDER>
__global__ void __launch_bounds__(256) sgemm_bias(
    const float* __restrict__ A, const float* __restrict__ W,
    const float* __restrict__ bias, float* __restrict__ C)
{
    __shared__ float As[8][128];
    __shared__ float Bs[8][128];

    const int bn = blockIdx.x, bm = blockIdx.y;
    const int tid = threadIdx.x;
    const int tx = tid & 15, ty = tid >> 4;
    const int m0 = bm * 128, n0 = bn * 128;

    // A-tile load: thread -> (row = tid/2, kcol = (tid&1)*4), one float4
    const int arow = tid >> 1;
    const int acol = (tid & 1) * 4;
    // B-tile load: thread -> (krow = tid/32, ncol = (tid&31)*4), one float4
    const int brow = tid >> 5;
    const int bcol = (tid & 31) * 4;

    const float* Aptr = A + (size_t)(m0 + arow) * E_ + acol;
    const float* Wptr = W + (size_t)brow * E_ + n0 + bcol;

    float acc[8][8];
    #pragma unroll
    for (int i = 0; i < 8; i++)
        #pragma unroll
        for (int j = 0; j < 8; j++) acc[i][j] = 0.f;

    for (int k0 = 0; k0 < E_; k0 += 8) {
        float4 a4 = *(const float4*)(Aptr + k0);
        float4 b4 = *(const float4*)(Wptr + (size_t)k0 * E_);
        As[acol + 0][arow] = a4.x;
        As[acol + 1][arow] = a4.y;
        As[acol + 2][arow] = a4.z;
        As[acol + 3][arow] = a4.w;
        *(float4*)&Bs[brow][bcol] = b4;
        __syncthreads();

        #pragma unroll
        for (int k = 0; k < 8; k++) {
            float ra[8], rb[8];
            *(float4*)&ra[0] = *(const float4*)&As[k][ty * 8];
            *(float4*)&ra[4] = *(const float4*)&As[k][ty * 8 + 4];
            *(float4*)&rb[0] = *(const float4*)&Bs[k][tx * 8];
            *(float4*)&rb[4] = *(const float4*)&Bs[k][tx * 8 + 4];
            #pragma unroll
            for (int i = 0; i < 8; i++)
                #pragma unroll
                for (int j = 0; j < 8; j++)
                    acc[i][j] += ra[i] * rb[j];
        }
        __syncthreads();
    }

    #pragma unroll
    for (int i = 0; i < 8; i++) {
        const int m = m0 + ty * 8 + i;
        #pragma unroll
        for (int j = 0; j < 8; j++) {
            const int n = n0 + tx * 8 + j;
            const float v = acc[i][j] + bias[n];
            if (REORDER) {
                const int b = m >> 11;        // m / T_
                const int t = m & (T_ - 1);
                const int h = n >> 6;         // n / HD_
                const int d = n & (HD_ - 1);
                C[(((size_t)(b * H_ + h) * T_) + t) * HD_ + d] = v;
            } else {
                C[(size_t)m * E_ + n] = v;
            }
        }
    }
}

// ---------------------------------------------------------------------------
// Flash attention (causal), fp32. One block = 64 query rows of one (b,h).
// KV tiles of 64. Online softmax. 256 threads (16x16), 4x4 per thread.
// Dynamic smem layout:
//   Qst [64][68]  (transposed: [d][r])
//   Kst [64][68]  (transposed: [d][c])
//   Vs  [64][64]  (natural:    [c][d])
//   Ss  [64][65]
//   m_s[64], l_s[64], corr_s[64]
// ---------------------------------------------------------------------------
#define QK_PAD 68
#define SS_PAD 65

__global__ void __launch_bounds__(256) attn_kernel(
    const float* __restrict__ Q, const float* __restrict__ K,
    const float* __restrict__ V, float* __restrict__ Y)
{
    extern __shared__ float smem[];
    float* Qst = smem;                       // 64*68
    float* Kst = Qst + 64 * QK_PAD;          // 64*68
    float* Vs  = Kst + 64 * QK_PAD;          // 64*64
    float* Ss  = Vs  + 64 * 64;              // 64*65
    float* m_s = Ss  + 64 * SS_PAD;          // 64
    float* l_s = m_s + 64;                   // 64
    float* corr_s = l_s + 64;                // 64

    const int qt = blockIdx.x;   // query tile (0..31)
    const int h  = blockIdx.y;
    const int b  = blockIdx.z;
    const int tid = threadIdx.x;
    const int tx = tid & 15, ty = tid >> 4;
    const int q0 = qt * 64;

    const size_t base = (size_t)(b * H_ + h) * T_ * HD_;
    const float* Qb = Q + base;
    const float* Kb = K + base;
    const float* Vb = V + base;

    // Load Q tile transposed
    for (int i = tid; i < 64 * 64; i += 256) {
        const int r = i >> 6, d = i & 63;
        Qst[d * QK_PAD + r] = Qb[(size_t)(q0 + r) * HD_ + d];
    }
    if (tid < 64) { m_s[tid] = -1e30f; l_s[tid] = 0.f; }

    float o[4][4];
    #pragma unroll
    for (int i = 0; i < 4; i++)
        #pragma unroll
        for (int j = 0; j < 4; j++) o[i][j] = 0.f;

    for (int kvt = 0; kvt <= qt; kvt++) {
        const int kv0 = kvt * 64;
        __syncthreads();  // previous phase-C readers done; Q load visible (1st iter)

        // Load K (transposed) and V (natural) tiles
        for (int i = tid; i < 64 * 64; i += 256) {
            const int c = i >> 6, d = i & 63;
            const float kv = Kb[(size_t)(kv0 + c) * HD_ + d];
            Kst[d * QK_PAD + c] = kv;
            Vs[c * 64 + d] = Vb[(size_t)(kv0 + c) * HD_ + d];
        }
        __syncthreads();

        // Phase A: S = Q @ K^T * 0.125, causal mask on diagonal tile
        float sacc[4][4];
        #pragma unroll
        for (int i = 0; i < 4; i++)
            #pragma unroll
            for (int j = 0; j < 4; j++) sacc[i][j] = 0.f;

        #pragma unroll 8
        for (int d = 0; d < 64; d++) {
            float4 qa = *(const float4*)&Qst[d * QK_PAD + ty * 4];
            float4 kb = *(const float4*)&Kst[d * QK_PAD + tx * 4];
            float ra[4] = {qa.x, qa.y, qa.z, qa.w};
            float rb[4] = {kb.x, kb.y, kb.z, kb.w};
            #pragma unroll
            for (int i = 0; i < 4; i++)
                #pragma unroll
                for (int j = 0; j < 4; j++)
                    sacc[i][j] += ra[i] * rb[j];
        }
        const bool diag = (kvt == qt);
        #pragma unroll
        for (int i = 0; i < 4; i++) {
            const int qi = ty * 4 + i;   // local row; global q0+qi
            #pragma unroll
            for (int j = 0; j < 4; j++) {
                const int kj = tx * 4 + j;
                float s = sacc[i][j] * 0.125f;
                if (diag && kj > qi) s = -1e30f;
                Ss[qi * SS_PAD + kj] = s;
            }
        }
        __syncthreads();

        // Phase B: per-row online softmax (64 threads, one row each)
        if (tid < 64) {
            const int row = tid;
            const float mo = m_s[row];
            float mx = mo;
            #pragma unroll 8
            for (int k = 0; k < 64; k++) mx = fmaxf(mx, Ss[row * SS_PAD + k]);
            float sum = 0.f;
            #pragma unroll 8
            for (int k = 0; k < 64; k++) {
                const float p = __expf(Ss[row * SS_PAD + k] - mx);
                Ss[row * SS_PAD + k] = p;
                sum += p;
            }
            const float corr = __expf(mo - mx);
            corr_s[row] = corr;
            l_s[row] = l_s[row] * corr + sum;
            m_s[row] = mx;
        }
        __syncthreads();

        // Phase C: O = O*corr + P @ V
        #pragma unroll
        for (int i = 0; i < 4; i++) {
            const float c = corr_s[ty * 4 + i];
            #pragma unroll
            for (int j = 0; j < 4; j++) o[i][j] *= c;
        }
        #pragma unroll 4
        for (int k = 0; k < 64; k++) {
            float4 v4 = *(const float4*)&Vs[k * 64 + tx * 4];
            float p[4];
            #pragma unroll
            for (int i = 0; i < 4; i++) p[i] = Ss[(ty * 4 + i) * SS_PAD + k];
            #pragma unroll
            for (int i = 0; i < 4; i++) {
                o[i][0] += p[i] * v4.x;
                o[i][1] += p[i] * v4.y;
                o[i][2] += p[i] * v4.z;
                o[i][3] += p[i] * v4.w;
            }
        }
    }

    // Epilogue: Y[b, q, h*64+d] = O / l  (layout [B,T,E] for final GEMM)
    #pragma unroll
    for (int i = 0; i < 4; i++) {
        const int r = ty * 4 + i;
        const float inv_l = 1.0f / l_s[r];
        const size_t row = (size_t)(b * T_ + q0 + r) * E_ + h * HD_;
        #pragma unroll
        for (int j = 0; j < 4; j++)
            Y[row + tx * 4 + j] = o[i][j] * inv_l;
    }
}

// ---------------------------------------------------------------------------
extern "C" void kernel_launch(void* const* d_in, const int* in_sizes, int n_in,
                              void* d_out, int out_size)
{
    const float* x  = (const float*)d_in[0];
    // d_in[1] = ch_list (unused)
    const float* Wq = (const float*)d_in[2];
    const float* bq = (const float*)d_in[3];
    const float* Wk = (const float*)d_in[4];
    const float* bk = (const float*)d_in[5];
    const float* Wv = (const float*)d_in[6];
    const float* bv = (const float*)d_in[7];
    const float* Wp = (const float*)d_in[8];
    const float* bp = (const float*)d_in[9];
    float* out = (float*)d_out;

    float *q, *k, *v, *y;
    cudaGetSymbolAddress((void**)&q, g_q);
    cudaGetSymbolAddress((void**)&k, g_k);
    cudaGetSymbolAddress((void**)&v, g_v);
    cudaGetSymbolAddress((void**)&y, g_y);

    const int smem_attn = (64 * QK_PAD * 2 + 64 * 64 + 64 * SS_PAD + 3 * 64) * (int)sizeof(float);
    cudaFuncSetAttribute(attn_kernel, cudaFuncAttributeMaxDynamicSharedMemorySize, smem_attn);

    dim3 gemm_grid(E_ / 128, M_ / 128);  // (8, 64)
    sgemm_bias<true><<<gemm_grid, 256>>>(x, Wq, bq, q);
    sgemm_bias<true><<<gemm_grid, 256>>>(x, Wk, bk, k);
    sgemm_bias<true><<<gemm_grid, 256>>>(x, Wv, bv, v);

    dim3 attn_grid(T_ / 64, H_, B_);     // (32, 16, 4)
    attn_kernel<<<attn_grid, 256, smem_attn>>>(q, k, v, y);

    sgemm_bias<false><<<gemm_grid, 256>>>(y, Wp, bp, out);
}

// round 3
// speedup vs baseline: 1.4681x; 1.4681x over previous
#include <cuda_runtime.h>
#include <cuda_bf16.h>
#include <stdint.h>
#include <math.h>

#define B_  4
#define T_  2048
#define E_  1024
#define H_  16
#define HD_ 64
#define M_  (B_*T_)   // 8192

// Scratch (device globals: allocation-free)
__device__ float g_q[M_*E_];
__device__ float g_k[M_*E_];
__device__ float g_v[M_*E_];
__device__ __nv_bfloat16 g_xh[M_*E_];
__device__ __nv_bfloat16 g_xl[M_*E_];
__device__ __nv_bfloat16 g_yh[M_*E_];
__device__ __nv_bfloat16 g_yl[M_*E_];
__device__ __nv_bfloat16 g_wqh[E_*E_], g_wql[E_*E_];
__device__ __nv_bfloat16 g_wkh[E_*E_], g_wkl[E_*E_];
__device__ __nv_bfloat16 g_wvh[E_*E_], g_wvl[E_*E_];
__device__ __nv_bfloat16 g_wph[E_*E_], g_wpl[E_*E_];

// ---------------------------------------------------------------------------
// helpers
// ---------------------------------------------------------------------------
__device__ __forceinline__ uint32_t smem_u32(const void* p) {
    return (uint32_t)__cvta_generic_to_shared(p);
}
__device__ __forceinline__ void cp_async16(uint32_t dst, const void* src) {
    asm volatile("cp.async.cg.shared.global [%0], [%1], 16;\n" :: "r"(dst), "l"(src));
}
__device__ __forceinline__ void cp_commit() {
    asm volatile("cp.async.commit_group;\n");
}
__device__ __forceinline__ void cp_wait0() {
    asm volatile("cp.async.wait_group 0;\n");
}
__device__ __forceinline__ void mma_bf16(float c[4], const uint32_t a[4], const uint32_t b[2]) {
    asm volatile(
        "mma.sync.aligned.m16n8k16.row.col.f32.bf16.bf16.f32 "
        "{%0,%1,%2,%3}, {%4,%5,%6,%7}, {%8,%9}, {%0,%1,%2,%3};\n"
        : "+f"(c[0]), "+f"(c[1]), "+f"(c[2]), "+f"(c[3])
        : "r"(a[0]), "r"(a[1]), "r"(a[2]), "r"(a[3]), "r"(b[0]), "r"(b[1]));
}
__device__ __forceinline__ void split_bf16(float v, __nv_bfloat16& h, __nv_bfloat16& l) {
    h = __float2bfloat16(v);
    l = __float2bfloat16(v - __bfloat162float(h));
}

// ---------------------------------------------------------------------------
// Prep: split fp32 -> bf16 hi/lo, same layout. n must be /4.
// ---------------------------------------------------------------------------
__global__ void split_kernel(const float* __restrict__ src,
                             __nv_bfloat16* __restrict__ hi,
                             __nv_bfloat16* __restrict__ lo, int n4)
{
    int i = blockIdx.x * blockDim.x + threadIdx.x;
    if (i >= n4) return;
    float4 v = ((const float4*)src)[i];
    __nv_bfloat16 h0,h1,h2,h3,l0,l1,l2,l3;
    split_bf16(v.x,h0,l0); split_bf16(v.y,h1,l1);
    split_bf16(v.z,h2,l2); split_bf16(v.w,h3,l3);
    ((__nv_bfloat162*)hi)[i*2+0] = __nv_bfloat162(h0,h1);
    ((__nv_bfloat162*)hi)[i*2+1] = __nv_bfloat162(h2,h3);
    ((__nv_bfloat162*)lo)[i*2+0] = __nv_bfloat162(l0,l1);
    ((__nv_bfloat162*)lo)[i*2+1] = __nv_bfloat162(l2,l3);
}

// ---------------------------------------------------------------------------
// Prep: transpose + split. W[K][N] fp32 -> Th/Tl[N][K] bf16.
// ---------------------------------------------------------------------------
__global__ void tsplit_kernel(const float* __restrict__ W,
                              __nv_bfloat16* __restrict__ Th,
                              __nv_bfloat16* __restrict__ Tl)
{
    __shared__ float t[32][33];
    const int n0 = blockIdx.x * 32, k0 = blockIdx.y * 32;
    const int tx = threadIdx.x, ty = threadIdx.y;   // (32, 8)
    #pragma unroll
    for (int i = 0; i < 4; i++)
        t[ty + 8*i][tx] = W[(size_t)(k0 + ty + 8*i) * E_ + n0 + tx];
    __syncthreads();
    #pragma unroll
    for (int i = 0; i < 4; i++) {
        const int row = ty + 8*i;                   // local n
        const float v = t[tx][row];                 // W[k0+tx][n0+row]
        __nv_bfloat16 h, l;
        split_bf16(v, h, l);
        Th[(size_t)(n0 + row) * E_ + k0 + tx] = h;
        Tl[(size_t)(n0 + row) * E_ + k0 + tx] = l;
    }
}

// ---------------------------------------------------------------------------
// bf16x3 tensor-core GEMM: C[M,N] = A[M,K] @ B^T + bias, fp32-accurate.
// A given as Ah/Al [M][K] bf16; B as Th/Tl [N][K] bf16 (pre-transposed).
// Block 128x128, BK=32 (16 k-pairs), 256 threads, warp tile 64x32.
// Smem per operand tile: [128 rows][20 uint32] (16 used + 4 pad).
// ---------------------------------------------------------------------------
#define ROW_U32 20
#define TILE_U32 (128*ROW_U32)                 // 2560
#define STAGE_U32 (4*TILE_U32)                 // 10240 (Ah, Al, Bh, Bl)

template<bool REORDER>
__global__ void __launch_bounds__(256) gemm_bf16x3(
    const __nv_bfloat16* __restrict__ Ah, const __nv_bfloat16* __restrict__ Al,
    const __nv_bfloat16* __restrict__ Th, const __nv_bfloat16* __restrict__ Tl,
    const float* __restrict__ bias, float* __restrict__ C)
{
    extern __shared__ uint32_t smem[];

    const int tid  = threadIdx.x;
    const int warp = tid >> 5;
    const int lane = tid & 31;
    const int group = lane >> 2;     // 0..7
    const int tidg  = lane & 3;      // 0..3

    const int bn = blockIdx.x, bm = blockIdx.y;
    const int m0 = bm * 128, n0 = bn * 128;
    const int warp_m = warp & 1;     // 64 rows each
    const int warp_n = warp >> 1;    // 32 cols each

    uint32_t* stg[2] = { smem, smem + STAGE_U32 };

    // 512 16B-chunks per tile; thread covers 2: f = tid + i*256
    auto load_stage = [&](int stage, int k0) {
        uint32_t* s = stg[stage];
        #pragma unroll
        for (int i = 0; i < 2; i++) {
            const int f = tid + i * 256;
            const int row = f >> 2, kq = f & 3;       // kq*8 bf16 elements
            const uint32_t dst = smem_u32(s + row * ROW_U32 + kq * 4);
            const size_t goff = (size_t)row * E_ + k0 + kq * 8;
            cp_async16(dst,                              Ah + (size_t)m0 * E_ + goff);
            cp_async16(dst + TILE_U32 * 4,               Al + (size_t)m0 * E_ + goff);
            cp_async16(dst + 2 * TILE_U32 * 4,           Th + (size_t)n0 * E_ + goff);
            cp_async16(dst + 3 * TILE_U32 * 4,           Tl + (size_t)n0 * E_ + goff);
        }
    };

    float acc[4][4][4];
    #pragma unroll
    for (int i = 0; i < 4; i++)
        #pragma unroll
        for (int j = 0; j < 4; j++)
            #pragma unroll
            for (int r = 0; r < 4; r++) acc[i][j][r] = 0.f;

    const int NT = E_ / 32;
    load_stage(0, 0);
    cp_commit();

    for (int it = 0; it < NT; it++) {
        cp_wait0();
        __syncthreads();
        if (it + 1 < NT) { load_stage((it + 1) & 1, (it + 1) * 32); cp_commit(); }

        const uint32_t* as_h = stg[it & 1];
        const uint32_t* as_l = as_h + TILE_U32;
        const uint32_t* bs_h = as_h + 2 * TILE_U32;
        const uint32_t* bs_l = as_h + 3 * TILE_U32;

        #pragma unroll
        for (int c = 0; c < 2; c++) {          // two k16 chunks
            const int kpb = c * 8;
            uint32_t ah[4][4], al[4][4], bh[4][2], bl[4][2];
            #pragma unroll
            for (int i = 0; i < 4; i++) {
                const int rb = (warp_m * 64 + i * 16 + group) * ROW_U32 + kpb + tidg;
                ah[i][0] = as_h[rb];            ah[i][1] = as_h[rb + 8 * ROW_U32];
                ah[i][2] = as_h[rb + 4];        ah[i][3] = as_h[rb + 8 * ROW_U32 + 4];
                al[i][0] = as_l[rb];            al[i][1] = as_l[rb + 8 * ROW_U32];
                al[i][2] = as_l[rb + 4];        al[i][3] = as_l[rb + 8 * ROW_U32 + 4];
            }
            #pragma unroll
            for (int j = 0; j < 4; j++) {
                const int cb = (warp_n * 32 + j * 8 + group) * ROW_U32 + kpb + tidg;
                bh[j][0] = bs_h[cb];            bh[j][1] = bs_h[cb + 4];
                bl[j][0] = bs_l[cb];            bl[j][1] = bs_l[cb + 4];
            }
            #pragma unroll
            for (int i = 0; i < 4; i++)
                #pragma unroll
                for (int j = 0; j < 4; j++) {
                    mma_bf16(acc[i][j], ah[i], bh[j]);
                    mma_bf16(acc[i][j], ah[i], bl[j]);
                    mma_bf16(acc[i][j], al[i], bh[j]);
                }
        }
        __syncthreads();
    }

    #pragma unroll
    for (int i = 0; i < 4; i++) {
        const int rmb = m0 + warp_m * 64 + i * 16 + group;
        #pragma unroll
        for (int j = 0; j < 4; j++) {
            const int cb = n0 + warp_n * 32 + j * 8 + tidg * 2;
            const float bx = bias[cb], by = bias[cb + 1];
            #pragma unroll
            for (int half = 0; half < 2; half++) {
                const int m = rmb + half * 8;
                float2 v;
                v.x = acc[i][j][half * 2 + 0] + bx;
                v.y = acc[i][j][half * 2 + 1] + by;
                if (REORDER) {
                    const int b = m >> 11;
                    const int t = m & (T_ - 1);
                    const int h = cb >> 6;
                    const int d = cb & (HD_ - 1);
                    *(float2*)&C[(((size_t)(b * H_ + h) * T_) + t) * HD_ + d] = v;
                } else {
                    *(float2*)&C[(size_t)m * E_ + cb] = v;
                }
            }
        }
    }
}

// ---------------------------------------------------------------------------
// Flash attention (causal), fp32. Epilogue writes split bf16 hi/lo for the
// output-projection GEMM.
// ---------------------------------------------------------------------------
#define QK_PAD 68
#define SS_PAD 65

__global__ void __launch_bounds__(256) attn_kernel(
    const float* __restrict__ Q, const float* __restrict__ K,
    const float* __restrict__ V,
    __nv_bfloat16* __restrict__ Yh, __nv_bfloat16* __restrict__ Yl)
{
    extern __shared__ float smf[];
    float* Qst = smf;
    float* Kst = Qst + 64 * QK_PAD;
    float* Vs  = Kst + 64 * QK_PAD;
    float* Ss  = Vs  + 64 * 64;
    float* m_s = Ss  + 64 * SS_PAD;
    float* l_s = m_s + 64;
    float* corr_s = l_s + 64;

    const int qt = blockIdx.x;
    const int h  = blockIdx.y;
    const int b  = blockIdx.z;
    const int tid = threadIdx.x;
    const int tx = tid & 15, ty = tid >> 4;
    const int q0 = qt * 64;

    const size_t base = (size_t)(b * H_ + h) * T_ * HD_;
    const float* Qb = Q + base;
    const float* Kb = K + base;
    const float* Vb = V + base;

    for (int i = tid; i < 64 * 64; i += 256) {
        const int r = i >> 6, d = i & 63;
        Qst[d * QK_PAD + r] = Qb[(size_t)(q0 + r) * HD_ + d];
    }
    if (tid < 64) { m_s[tid] = -1e30f; l_s[tid] = 0.f; }

    float o[4][4];
    #pragma unroll
    for (int i = 0; i < 4; i++)
        #pragma unroll
        for (int j = 0; j < 4; j++) o[i][j] = 0.f;

    for (int kvt = 0; kvt <= qt; kvt++) {
        const int kv0 = kvt * 64;
        __syncthreads();

        for (int i = tid; i < 64 * 64; i += 256) {
            const int c = i >> 6, d = i & 63;
            const float kv = Kb[(size_t)(kv0 + c) * HD_ + d];
            Kst[d * QK_PAD + c] = kv;
            Vs[c * 64 + d] = Vb[(size_t)(kv0 + c) * HD_ + d];
        }
        __syncthreads();

        float sacc[4][4];
        #pragma unroll
        for (int i = 0; i < 4; i++)
            #pragma unroll
            for (int j = 0; j < 4; j++) sacc[i][j] = 0.f;

        #pragma unroll 8
        for (int d = 0; d < 64; d++) {
            float4 qa = *(const float4*)&Qst[d * QK_PAD + ty * 4];
            float4 kb = *(const float4*)&Kst[d * QK_PAD + tx * 4];
            float ra[4] = {qa.x, qa.y, qa.z, qa.w};
            float rb[4] = {kb.x, kb.y, kb.z, kb.w};
            #pragma unroll
            for (int i = 0; i < 4; i++)
                #pragma unroll
                for (int j = 0; j < 4; j++)
                    sacc[i][j] += ra[i] * rb[j];
        }
        const bool diag = (kvt == qt);
        #pragma unroll
        for (int i = 0; i < 4; i++) {
            const int qi = ty * 4 + i;
            #pragma unroll
            for (int j = 0; j < 4; j++) {
                const int kj = tx * 4 + j;
                float s = sacc[i][j] * 0.125f;
                if (diag && kj > qi) s = -1e30f;
                Ss[qi * SS_PAD + kj] = s;
            }
        }
        __syncthreads();

        if (tid < 64) {
            const int row = tid;
            const float mo = m_s[row];
            float mx = mo;
            #pragma unroll 8
            for (int k = 0; k < 64; k++) mx = fmaxf(mx, Ss[row * SS_PAD + k]);
            float sum = 0.f;
            #pragma unroll 8
            for (int k = 0; k < 64; k++) {
                const float p = __expf(Ss[row * SS_PAD + k] - mx);
                Ss[row * SS_PAD + k] = p;
                sum += p;
            }
            const float corr = __expf(mo - mx);
            corr_s[row] = corr;
            l_s[row] = l_s[row] * corr + sum;
            m_s[row] = mx;
        }
        __syncthreads();

        #pragma unroll
        for (int i = 0; i < 4; i++) {
            const float c = corr_s[ty * 4 + i];
            #pragma unroll
            for (int j = 0; j < 4; j++) o[i][j] *= c;
        }
        #pragma unroll 4
        for (int k = 0; k < 64; k++) {
            float4 v4 = *(const float4*)&Vs[k * 64 + tx * 4];
            float p[4];
            #pragma unroll
            for (int i = 0; i < 4; i++) p[i] = Ss[(ty * 4 + i) * SS_PAD + k];
            #pragma unroll
            for (int i = 0; i < 4; i++) {
                o[i][0] += p[i] * v4.x;
                o[i][1] += p[i] * v4.y;
                o[i][2] += p[i] * v4.z;
                o[i][3] += p[i] * v4.w;
            }
        }
    }

    #pragma unroll
    for (int i = 0; i < 4; i++) {
        const int r = ty * 4 + i;
        const float inv_l = 1.0f / l_s[r];
        const size_t row = (size_t)(b * T_ + q0 + r) * E_ + h * HD_ + tx * 4;
        __nv_bfloat16 hh[4], ll[4];
        #pragma unroll
        for (int j = 0; j < 4; j++) split_bf16(o[i][j] * inv_l, hh[j], ll[j]);
        *(__nv_bfloat162*)&Yh[row]     = __nv_bfloat162(hh[0], hh[1]);
        *(__nv_bfloat162*)&Yh[row + 2] = __nv_bfloat162(hh[2], hh[3]);
        *(__nv_bfloat162*)&Yl[row]     = __nv_bfloat162(ll[0], ll[1]);
        *(__nv_bfloat162*)&Yl[row + 2] = __nv_bfloat162(ll[2], ll[3]);
    }
}

// ---------------------------------------------------------------------------
extern "C" void kernel_launch(void* const* d_in, const int* in_sizes, int n_in,
                              void* d_out, int out_size)
{
    const float* x  = (const float*)d_in[0];
    const float* Wq = (const float*)d_in[2];
    const float* bq = (const float*)d_in[3];
    const float* Wk = (const float*)d_in[4];
    const float* bk = (const float*)d_in[5];
    const float* Wv = (const float*)d_in[6];
    const float* bv = (const float*)d_in[7];
    const float* Wp = (const float*)d_in[8];
    const float* bp = (const float*)d_in[9];
    float* out = (float*)d_out;

    float *q, *k, *v;
    __nv_bfloat16 *xh, *xl, *yh, *yl;
    __nv_bfloat16 *wqh, *wql, *wkh, *wkl, *wvh, *wvl, *wph, *wpl;
    cudaGetSymbolAddress((void**)&q, g_q);
    cudaGetSymbolAddress((void**)&k, g_k);
    cudaGetSymbolAddress((void**)&v, g_v);
    cudaGetSymbolAddress((void**)&xh, g_xh);
    cudaGetSymbolAddress((void**)&xl, g_xl);
    cudaGetSymbolAddress((void**)&yh, g_yh);
    cudaGetSymbolAddress((void**)&yl, g_yl);
    cudaGetSymbolAddress((void**)&wqh, g_wqh);  cudaGetSymbolAddress((void**)&wql, g_wql);
    cudaGetSymbolAddress((void**)&wkh, g_wkh);  cudaGetSymbolAddress((void**)&wkl, g_wkl);
    cudaGetSymbolAddress((void**)&wvh, g_wvh);  cudaGetSymbolAddress((void**)&wvl, g_wvl);
    cudaGetSymbolAddress((void**)&wph, g_wph);  cudaGetSymbolAddress((void**)&wpl, g_wpl);

    const int smem_gemm = 2 * STAGE_U32 * (int)sizeof(uint32_t);   // 80 KB
    cudaFuncSetAttribute(gemm_bf16x3<true>,  cudaFuncAttributeMaxDynamicSharedMemorySize, smem_gemm);
    cudaFuncSetAttribute(gemm_bf16x3<false>, cudaFuncAttributeMaxDynamicSharedMemorySize, smem_gemm);

    const int smem_attn = (64 * QK_PAD * 2 + 64 * 64 + 64 * SS_PAD + 3 * 64) * (int)sizeof(float);
    cudaFuncSetAttribute(attn_kernel, cudaFuncAttributeMaxDynamicSharedMemorySize, smem_attn);

    // Prep: split x, transpose+split weights
    split_kernel<<<(M_*E_/4 + 255)/256, 256>>>(x, xh, xl, M_*E_/4);
    dim3 tgrid(E_/32, E_/32), tblk(32, 8);
    tsplit_kernel<<<tgrid, tblk>>>(Wq, wqh, wql);
    tsplit_kernel<<<tgrid, tblk>>>(Wk, wkh, wkl);
    tsplit_kernel<<<tgrid, tblk>>>(Wv, wvh, wvl);
    tsplit_kernel<<<tgrid, tblk>>>(Wp, wph, wpl);

    dim3 gemm_grid(E_ / 128, M_ / 128);  // (8, 64)
    gemm_bf16x3<true><<<gemm_grid, 256, smem_gemm>>>(xh, xl, wqh, wql, bq, q);
    gemm_bf16x3<true><<<gemm_grid, 256, smem_gemm>>>(xh, xl, wkh, wkl, bk, k);
    gemm_bf16x3<true><<<gemm_grid, 256, smem_gemm>>>(xh, xl, wvh, wvl, bv, v);

    dim3 attn_grid(T_ / 64, H_, B_);     // (32, 16, 4)
    attn_kernel<<<attn_grid, 256, smem_attn>>>(q, k, v, yh, yl);

    gemm_bf16x3<false><<<gemm_grid, 256, smem_gemm>>>(yh, yl, wph, wpl, bp, out);
}

// round 5
// speedup vs baseline: 1.4728x; 1.0032x over previous
#include <cuda_runtime.h>
#include <cuda_bf16.h>
#include <stdint.h>
#include <math.h>

#define B_  4
#define T_  2048
#define E_  1024
#define H_  16
#define HD_ 64
#define M_  (B_*T_)   // 8192

// Scratch (device globals: allocation-free)
__device__ float g_q[M_*E_];
__device__ float g_k[M_*E_];
__device__ float g_v[M_*E_];
__device__ __nv_bfloat16 g_xh[M_*E_];
__device__ __nv_bfloat16 g_xl[M_*E_];
__device__ __nv_bfloat16 g_yh[M_*E_];
__device__ __nv_bfloat16 g_yl[M_*E_];
__device__ __nv_bfloat16 g_wqh[E_*E_], g_wql[E_*E_];
__device__ __nv_bfloat16 g_wkh[E_*E_], g_wkl[E_*E_];
__device__ __nv_bfloat16 g_wvh[E_*E_], g_wvl[E_*E_];
__device__ __nv_bfloat16 g_wph[E_*E_], g_wpl[E_*E_];

// ---------------------------------------------------------------------------
// helpers
// ---------------------------------------------------------------------------
__device__ __forceinline__ uint32_t smem_u32(const void* p) {
    return (uint32_t)__cvta_generic_to_shared(p);
}
__device__ __forceinline__ void cp_async16(uint32_t dst, const void* src) {
    asm volatile("cp.async.cg.shared.global [%0], [%1], 16;\n" :: "r"(dst), "l"(src));
}
__device__ __forceinline__ void cp_commit() {
    asm volatile("cp.async.commit_group;\n");
}
__device__ __forceinline__ void cp_wait0() { asm volatile("cp.async.wait_group 0;\n"); }
__device__ __forceinline__ void cp_wait1() { asm volatile("cp.async.wait_group 1;\n"); }
__device__ __forceinline__ void cp_wait2() { asm volatile("cp.async.wait_group 2;\n"); }

__device__ __forceinline__ void mma_bf16(float c[4], const uint32_t a[4], uint32_t b0, uint32_t b1) {
    asm volatile(
        "mma.sync.aligned.m16n8k16.row.col.f32.bf16.bf16.f32 "
        "{%0,%1,%2,%3}, {%4,%5,%6,%7}, {%8,%9}, {%0,%1,%2,%3};\n"
        : "+f"(c[0]), "+f"(c[1]), "+f"(c[2]), "+f"(c[3])
        : "r"(a[0]), "r"(a[1]), "r"(a[2]), "r"(a[3]), "r"(b0), "r"(b1));
}
__device__ __forceinline__ void ldsm_x4(uint32_t r[4], uint32_t addr) {
    asm volatile("ldmatrix.sync.aligned.m8n8.x4.shared.b16 {%0,%1,%2,%3}, [%4];"
        : "=r"(r[0]), "=r"(r[1]), "=r"(r[2]), "=r"(r[3]) : "r"(addr));
}
__device__ __forceinline__ void split_bf16(float v, __nv_bfloat16& h, __nv_bfloat16& l) {
    h = __float2bfloat16(v);
    l = __float2bfloat16(v - __bfloat162float(h));
}

// ---------------------------------------------------------------------------
// Prep: split fp32 -> bf16 hi/lo, same layout.
// ---------------------------------------------------------------------------
__global__ void split_kernel(const float* __restrict__ src,
                             __nv_bfloat16* __restrict__ hi,
                             __nv_bfloat16* __restrict__ lo, int n4)
{
    int i = blockIdx.x * blockDim.x + threadIdx.x;
    if (i >= n4) return;
    float4 v = ((const float4*)src)[i];
    __nv_bfloat16 h0,h1,h2,h3,l0,l1,l2,l3;
    split_bf16(v.x,h0,l0); split_bf16(v.y,h1,l1);
    split_bf16(v.z,h2,l2); split_bf16(v.w,h3,l3);
    ((__nv_bfloat162*)hi)[i*2+0] = __nv_bfloat162(h0,h1);
    ((__nv_bfloat162*)hi)[i*2+1] = __nv_bfloat162(h2,h3);
    ((__nv_bfloat162*)lo)[i*2+0] = __nv_bfloat162(l0,l1);
    ((__nv_bfloat162*)lo)[i*2+1] = __nv_bfloat162(l2,l3);
}

// ---------------------------------------------------------------------------
// Prep: transpose + split. W[K][N] fp32 -> Th/Tl[N][K] bf16.
// ---------------------------------------------------------------------------
__global__ void tsplit_kernel(const float* __restrict__ W,
                              __nv_bfloat16* __restrict__ Th,
                              __nv_bfloat16* __restrict__ Tl)
{
    __shared__ float t[32][33];
    const int n0 = blockIdx.x * 32, k0 = blockIdx.y * 32;
    const int tx = threadIdx.x, ty = threadIdx.y;   // (32, 8)
    #pragma unroll
    for (int i = 0; i < 4; i++)
        t[ty + 8*i][tx] = W[(size_t)(k0 + ty + 8*i) * E_ + n0 + tx];
    __syncthreads();
    #pragma unroll
    for (int i = 0; i < 4; i++) {
        const int row = ty + 8*i;
        const float v = t[tx][row];
        __nv_bfloat16 h, l;
        split_bf16(v, h, l);
        Th[(size_t)(n0 + row) * E_ + k0 + tx] = h;
        Tl[(size_t)(n0 + row) * E_ + k0 + tx] = l;
    }
}

// ---------------------------------------------------------------------------
// bf16x3 tensor-core GEMM with ldmatrix + 3-stage cp.async.
// C[M,N] = A @ W + bias; A = Ah+Al [M][K]; W^T = Th+Tl [N][K].
// Block 128x128, BK=32, 256 threads (8 warps), warp tile 64x32.
// Smem tile row stride 80 B (64 B data + 16 pad) -> ldsm conflict-free.
// ---------------------------------------------------------------------------
#define GS_STRIDE 80
#define GS_TILE   (128*GS_STRIDE)      // 10240 B
#define GS_STAGE  (4*GS_TILE)          // 40960 B (Ah, Al, Bh, Bl)
#define GS_SMEM   (3*GS_STAGE)         // 122880 B

template<bool REORDER>
__global__ void __launch_bounds__(256) gemm_bf16x3(
    const __nv_bfloat16* __restrict__ Ah, const __nv_bfloat16* __restrict__ Al,
    const __nv_bfloat16* __restrict__ Th, const __nv_bfloat16* __restrict__ Tl,
    const float* __restrict__ bias, float* __restrict__ C)
{
    extern __shared__ char sm[];
    const uint32_t smb = smem_u32(sm);

    const int tid  = threadIdx.x;
    const int warp = tid >> 5;
    const int lane = tid & 31;
    const int group = lane >> 2;     // 0..7
    const int tidg  = lane & 3;      // 0..3

    const int bn = blockIdx.x, bm = blockIdx.y;
    const int m0 = bm * 128, n0 = bn * 128;
    const int warp_m = warp & 1;     // 64 rows each
    const int warp_n = warp >> 1;    // 32 cols each

    // ldmatrix lane addressing: matrix id = lane>>3
    const int lrow = (lane & 7) + ((lane >> 3) & 1) * 8;
    const int lkb  = ((lane >> 4) & 1) * 16;

    auto load_stage = [&](int s, int c) {
        const int kb = c * 32;
        const uint32_t st = smb + s * GS_STAGE;
        #pragma unroll
        for (int i = 0; i < 2; i++) {
            const int ch = tid + i * 256;          // 0..511
            const int row = ch >> 2, q = ch & 3;
            const uint32_t d = st + row * GS_STRIDE + q * 16;
            const size_t ga = (size_t)(m0 + row) * E_ + kb + q * 8;
            const size_t gb = (size_t)(n0 + row) * E_ + kb + q * 8;
            cp_async16(d,               Ah + ga);
            cp_async16(d + GS_TILE,     Al + ga);
            cp_async16(d + 2*GS_TILE,   Th + gb);
            cp_async16(d + 3*GS_TILE,   Tl + gb);
        }
        cp_commit();
    };

    float acc[4][4][4];
    #pragma unroll
    for (int i = 0; i < 4; i++)
        #pragma unroll
        for (int j = 0; j < 4; j++)
            #pragma unroll
            for (int r = 0; r < 4; r++) acc[i][j][r] = 0.f;

    const int NC = E_ / 32;   // 32
    load_stage(0, 0);
    load_stage(1, 1);
    load_stage(2, 2);

    int s = 0;
    for (int c = 0; c < NC; c++) {
        if (c >= NC - 1)      cp_wait0();
        else if (c >= NC - 2) cp_wait1();
        else                  cp_wait2();
        __syncthreads();

        const uint32_t st = smb + s * GS_STAGE;
        const uint32_t abase = st + (warp_m * 64 + lrow) * GS_STRIDE + lkb;
        const uint32_t bbase = st + 2*GS_TILE + (warp_n * 32 + lrow) * GS_STRIDE + lkb;

        #pragma unroll
        for (int h2 = 0; h2 < 2; h2++) {       // two k16 halves of BK=32
            const int ko = h2 * 32;            // bytes
            uint32_t ah[4][4], al[4][4], bh[2][4], bl[2][4];
            #pragma unroll
            for (int i = 0; i < 4; i++) {
                ldsm_x4(ah[i], abase + i * 16 * GS_STRIDE + ko);
                ldsm_x4(al[i], abase + GS_TILE + i * 16 * GS_STRIDE + ko);
            }
            #pragma unroll
            for (int g = 0; g < 2; g++) {
                ldsm_x4(bh[g], bbase + g * 16 * GS_STRIDE + ko);
                ldsm_x4(bl[g], bbase + GS_TILE + g * 16 * GS_STRIDE + ko);
            }
            // product-major: acc touched every 16 mma -> no RAW stalls
            #pragma unroll
            for (int i = 0; i < 4; i++)
                #pragma unroll
                for (int j = 0; j < 4; j++)
                    mma_bf16(acc[i][j], ah[i], bh[j>>1][j&1], bh[j>>1][(j&1)+2]);
            #pragma unroll
            for (int i = 0; i < 4; i++)
                #pragma unroll
                for (int j = 0; j < 4; j++)
                    mma_bf16(acc[i][j], ah[i], bl[j>>1][j&1], bl[j>>1][(j&1)+2]);
            #pragma unroll
            for (int i = 0; i < 4; i++)
                #pragma unroll
                for (int j = 0; j < 4; j++)
                    mma_bf16(acc[i][j], al[i], bh[j>>1][j&1], bh[j>>1][(j&1)+2]);
        }
        __syncthreads();
        if (c + 3 < NC) load_stage(s, c + 3);
        s = (s == 2) ? 0 : s + 1;
    }

    // Epilogue (mma C fragment layout)
    #pragma unroll
    for (int i = 0; i < 4; i++) {
        const int rmb = m0 + warp_m * 64 + i * 16 + group;
        #pragma unroll
        for (int j = 0; j < 4; j++) {
            const int cb = n0 + warp_n * 32 + j * 8 + tidg * 2;
            const float bx = bias[cb], by = bias[cb + 1];
            #pragma unroll
            for (int half = 0; half < 2; half++) {
                const int m = rmb + half * 8;
                float2 v;
                v.x = acc[i][j][half * 2 + 0] + bx;
                v.y = acc[i][j][half * 2 + 1] + by;
                if (REORDER) {
                    const int b = m >> 11;
                    const int t = m & (T_ - 1);
                    const int h = cb >> 6;
                    const int d = cb & (HD_ - 1);
                    *(float2*)&C[(((size_t)(b * H_ + h) * T_) + t) * HD_ + d] = v;
                } else {
                    *(float2*)&C[(size_t)m * E_ + cb] = v;
                }
            }
        }
    }
}

// ---------------------------------------------------------------------------
// Flash attention (causal), fp32. Epilogue writes split bf16 hi/lo.
// ---------------------------------------------------------------------------
#define QK_PAD 68
#define SS_PAD 65

__global__ void __launch_bounds__(256) attn_kernel(
    const float* __restrict__ Q, const float* __restrict__ K,
    const float* __restrict__ V,
    __nv_bfloat16* __restrict__ Yh, __nv_bfloat16* __restrict__ Yl)
{
    extern __shared__ float smf[];
    float* Qst = smf;
    float* Kst = Qst + 64 * QK_PAD;
    float* Vs  = Kst + 64 * QK_PAD;
    float* Ss  = Vs  + 64 * 64;
    float* m_s = Ss  + 64 * SS_PAD;
    float* l_s = m_s + 64;
    float* corr_s = l_s + 64;

    const int qt = blockIdx.x;
    const int h  = blockIdx.y;
    const int b  = blockIdx.z;
    const int tid = threadIdx.x;
    const int tx = tid & 15, ty = tid >> 4;
    const int q0 = qt * 64;

    const size_t base = (size_t)(b * H_ + h) * T_ * HD_;
    const float* Qb = Q + base;
    const float* Kb = K + base;
    const float* Vb = V + base;

    for (int i = tid; i < 64 * 64; i += 256) {
        const int r = i >> 6, d = i & 63;
        Qst[d * QK_PAD + r] = Qb[(size_t)(q0 + r) * HD_ + d];
    }
    if (tid < 64) { m_s[tid] = -1e30f; l_s[tid] = 0.f; }

    float o[4][4];
    #pragma unroll
    for (int i = 0; i < 4; i++)
        #pragma unroll
        for (int j = 0; j < 4; j++) o[i][j] = 0.f;

    for (int kvt = 0; kvt <= qt; kvt++) {
        const int kv0 = kvt * 64;
        __syncthreads();

        for (int i = tid; i < 64 * 64; i += 256) {
            const int c = i >> 6, d = i & 63;
            const float kv = Kb[(size_t)(kv0 + c) * HD_ + d];
            Kst[d * QK_PAD + c] = kv;
            Vs[c * 64 + d] = Vb[(size_t)(kv0 + c) * HD_ + d];
        }
        __syncthreads();

        float sacc[4][4];
        #pragma unroll
        for (int i = 0; i < 4; i++)
            #pragma unroll
            for (int j = 0; j < 4; j++) sacc[i][j] = 0.f;

        #pragma unroll 8
        for (int d = 0; d < 64; d++) {
            float4 qa = *(const float4*)&Qst[d * QK_PAD + ty * 4];
            float4 kb = *(const float4*)&Kst[d * QK_PAD + tx * 4];
            float ra[4] = {qa.x, qa.y, qa.z, qa.w};
            float rb[4] = {kb.x, kb.y, kb.z, kb.w};
            #pragma unroll
            for (int i = 0; i < 4; i++)
                #pragma unroll
                for (int j = 0; j < 4; j++)
                    sacc[i][j] += ra[i] * rb[j];
        }
        const bool diag = (kvt == qt);
        #pragma unroll
        for (int i = 0; i < 4; i++) {
            const int qi = ty * 4 + i;
            #pragma unroll
            for (int j = 0; j < 4; j++) {
                const int kj = tx * 4 + j;
                float s = sacc[i][j] * 0.125f;
                if (diag && kj > qi) s = -1e30f;
                Ss[qi * SS_PAD + kj] = s;
            }
        }
        __syncthreads();

        if (tid < 64) {
            const int row = tid;
            const float mo = m_s[row];
            float mx = mo;
            #pragma unroll 8
            for (int k = 0; k < 64; k++) mx = fmaxf(mx, Ss[row * SS_PAD + k]);
            float sum = 0.f;
            #pragma unroll 8
            for (int k = 0; k < 64; k++) {
                const float p = __expf(Ss[row * SS_PAD + k] - mx);
                Ss[row * SS_PAD + k] = p;
                sum += p;
            }
            const float corr = __expf(mo - mx);
            corr_s[row] = corr;
            l_s[row] = l_s[row] * corr + sum;
            m_s[row] = mx;
        }
        __syncthreads();

        #pragma unroll
        for (int i = 0; i < 4; i++) {
            const float c = corr_s[ty * 4 + i];
            #pragma unroll
            for (int j = 0; j < 4; j++) o[i][j] *= c;
        }
        #pragma unroll 4
        for (int k = 0; k < 64; k++) {
            float4 v4 = *(const float4*)&Vs[k * 64 + tx * 4];
            float p[4];
            #pragma unroll
            for (int i = 0; i < 4; i++) p[i] = Ss[(ty * 4 + i) * SS_PAD + k];
            #pragma unroll
            for (int i = 0; i < 4; i++) {
                o[i][0] += p[i] * v4.x;
                o[i][1] += p[i] * v4.y;
                o[i][2] += p[i] * v4.z;
                o[i][3] += p[i] * v4.w;
            }
        }
    }

    #pragma unroll
    for (int i = 0; i < 4; i++) {
        const int r = ty * 4 + i;
        const float inv_l = 1.0f / l_s[r];
        const size_t row = (size_t)(b * T_ + q0 + r) * E_ + h * HD_ + tx * 4;
        __nv_bfloat16 hh[4], ll[4];
        #pragma unroll
        for (int j = 0; j < 4; j++) split_bf16(o[i][j] * inv_l, hh[j], ll[j]);
        *(__nv_bfloat162*)&Yh[row]     = __nv_bfloat162(hh[0], hh[1]);
        *(__nv_bfloat162*)&Yh[row + 2] = __nv_bfloat162(hh[2], hh[3]);
        *(__nv_bfloat162*)&Yl[row]     = __nv_bfloat162(ll[0], ll[1]);
        *(__nv_bfloat162*)&Yl[row + 2] = __nv_bfloat162(ll[2], ll[3]);
    }
}

// ---------------------------------------------------------------------------
extern "C" void kernel_launch(void* const* d_in, const int* in_sizes, int n_in,
                              void* d_out, int out_size)
{
    const float* x  = (const float*)d_in[0];
    const float* Wq = (const float*)d_in[2];
    const float* bq = (const float*)d_in[3];
    const float* Wk = (const float*)d_in[4];
    const float* bk = (const float*)d_in[5];
    const float* Wv = (const float*)d_in[6];
    const float* bv = (const float*)d_in[7];
    const float* Wp = (const float*)d_in[8];
    const float* bp = (const float*)d_in[9];
    float* out = (float*)d_out;

    float *q, *k, *v;
    __nv_bfloat16 *xh, *xl, *yh, *yl;
    __nv_bfloat16 *wqh, *wql, *wkh, *wkl, *wvh, *wvl, *wph, *wpl;
    cudaGetSymbolAddress((void**)&q, g_q);
    cudaGetSymbolAddress((void**)&k, g_k);
    cudaGetSymbolAddress((void**)&v, g_v);
    cudaGetSymbolAddress((void**)&xh, g_xh);
    cudaGetSymbolAddress((void**)&xl, g_xl);
    cudaGetSymbolAddress((void**)&yh, g_yh);
    cudaGetSymbolAddress((void**)&yl, g_yl);
    cudaGetSymbolAddress((void**)&wqh, g_wqh);  cudaGetSymbolAddress((void**)&wql, g_wql);
    cudaGetSymbolAddress((void**)&wkh, g_wkh);  cudaGetSymbolAddress((void**)&wkl, g_wkl);
    cudaGetSymbolAddress((void**)&wvh, g_wvh);  cudaGetSymbolAddress((void**)&wvl, g_wvl);
    cudaGetSymbolAddress((void**)&wph, g_wph);  cudaGetSymbolAddress((void**)&wpl, g_wpl);

    cudaFuncSetAttribute(gemm_bf16x3<true>,  cudaFuncAttributeMaxDynamicSharedMemorySize, GS_SMEM);
    cudaFuncSetAttribute(gemm_bf16x3<false>, cudaFuncAttributeMaxDynamicSharedMemorySize, GS_SMEM);

    const int smem_attn = (64 * QK_PAD * 2 + 64 * 64 + 64 * SS_PAD + 3 * 64) * (int)sizeof(float);
    cudaFuncSetAttribute(attn_kernel, cudaFuncAttributeMaxDynamicSharedMemorySize, smem_attn);

    // Prep: split x, transpose+split weights
    split_kernel<<<(M_*E_/4 + 255)/256, 256>>>(x, xh, xl, M_*E_/4);
    dim3 tgrid(E_/32, E_/32), tblk(32, 8);
    tsplit_kernel<<<tgrid, tblk>>>(Wq, wqh, wql);
    tsplit_kernel<<<tgrid, tblk>>>(Wk, wkh, wkl);
    tsplit_kernel<<<tgrid, tblk>>>(Wv, wvh, wvl);
    tsplit_kernel<<<tgrid, tblk>>>(Wp, wph, wpl);

    dim3 gemm_grid(E_ / 128, M_ / 128);  // (8, 64)
    gemm_bf16x3<true><<<gemm_grid, 256, GS_SMEM>>>(xh, xl, wqh, wql, bq, q);
    gemm_bf16x3<true><<<gemm_grid, 256, GS_SMEM>>>(xh, xl, wkh, wkl, bk, k);
    gemm_bf16x3<true><<<gemm_grid, 256, GS_SMEM>>>(xh, xl, wvh, wvl, bv, v);

    dim3 attn_grid(T_ / 64, H_, B_);     // (32, 16, 4)
    attn_kernel<<<attn_grid, 256, smem_attn>>>(q, k, v, yh, yl);

    gemm_bf16x3<false><<<gemm_grid, 256, GS_SMEM>>>(yh, yl, wph, wpl, bp, out);
}

// round 6
// speedup vs baseline: 2.3257x; 1.5791x over previous
#include <cuda_runtime.h>
#include <cuda_bf16.h>
#include <stdint.h>
#include <math.h>

#define B_  4
#define T_  2048
#define E_  1024
#define H_  16
#define HD_ 64
#define M_  (B_*T_)   // 8192

// Scratch (device globals: allocation-free)
__device__ __nv_bfloat16 g_xh[M_*E_], g_xl[M_*E_];
__device__ __nv_bfloat16 g_yh[M_*E_], g_yl[M_*E_];
__device__ __nv_bfloat16 g_qh[M_*E_], g_ql[M_*E_];
__device__ __nv_bfloat16 g_kh[M_*E_], g_kl[M_*E_];
__device__ __nv_bfloat16 g_vh[M_*E_], g_vl[M_*E_];
__device__ __nv_bfloat16 g_wqh[E_*E_], g_wql[E_*E_];
__device__ __nv_bfloat16 g_wkh[E_*E_], g_wkl[E_*E_];
__device__ __nv_bfloat16 g_wvh[E_*E_], g_wvl[E_*E_];
__device__ __nv_bfloat16 g_wph[E_*E_], g_wpl[E_*E_];

// ---------------------------------------------------------------------------
// helpers
// ---------------------------------------------------------------------------
__device__ __forceinline__ uint32_t smem_u32(const void* p) {
    return (uint32_t)__cvta_generic_to_shared(p);
}
__device__ __forceinline__ void cp_async16(uint32_t dst, const void* src) {
    asm volatile("cp.async.cg.shared.global [%0], [%1], 16;\n" :: "r"(dst), "l"(src));
}
__device__ __forceinline__ void cp_commit() { asm volatile("cp.async.commit_group;\n"); }
__device__ __forceinline__ void cp_wait0() { asm volatile("cp.async.wait_group 0;\n"); }
__device__ __forceinline__ void cp_wait1() { asm volatile("cp.async.wait_group 1;\n"); }
__device__ __forceinline__ void cp_wait2() { asm volatile("cp.async.wait_group 2;\n"); }

__device__ __forceinline__ void mma_bf16(float c[4], const uint32_t a[4], uint32_t b0, uint32_t b1) {
    asm volatile(
        "mma.sync.aligned.m16n8k16.row.col.f32.bf16.bf16.f32 "
        "{%0,%1,%2,%3}, {%4,%5,%6,%7}, {%8,%9}, {%0,%1,%2,%3};\n"
        : "+f"(c[0]), "+f"(c[1]), "+f"(c[2]), "+f"(c[3])
        : "r"(a[0]), "r"(a[1]), "r"(a[2]), "r"(a[3]), "r"(b0), "r"(b1));
}
__device__ __forceinline__ void ldsm_x4(uint32_t r[4], uint32_t addr) {
    asm volatile("ldmatrix.sync.aligned.m8n8.x4.shared.b16 {%0,%1,%2,%3}, [%4];"
        : "=r"(r[0]), "=r"(r[1]), "=r"(r[2]), "=r"(r[3]) : "r"(addr));
}
__device__ __forceinline__ void ldsm_x4t(uint32_t r[4], uint32_t addr) {
    asm volatile("ldmatrix.sync.aligned.m8n8.x4.trans.shared.b16 {%0,%1,%2,%3}, [%4];"
        : "=r"(r[0]), "=r"(r[1]), "=r"(r[2]), "=r"(r[3]) : "r"(addr));
}
__device__ __forceinline__ void split_bf16(float v, __nv_bfloat16& h, __nv_bfloat16& l) {
    h = __float2bfloat16(v);
    l = __float2bfloat16(v - __bfloat162float(h));
}
__device__ __forceinline__ uint32_t pack_bf162(__nv_bfloat16 a, __nv_bfloat16 b) {
    __nv_bfloat162 p(a, b);
    return *(uint32_t*)&p;
}

// ---------------------------------------------------------------------------
// Prep: split fp32 -> bf16 hi/lo, same layout.
// ---------------------------------------------------------------------------
__global__ void split_kernel(const float* __restrict__ src,
                             __nv_bfloat16* __restrict__ hi,
                             __nv_bfloat16* __restrict__ lo, int n4)
{
    int i = blockIdx.x * blockDim.x + threadIdx.x;
    if (i >= n4) return;
    float4 v = ((const float4*)src)[i];
    __nv_bfloat16 h0,h1,h2,h3,l0,l1,l2,l3;
    split_bf16(v.x,h0,l0); split_bf16(v.y,h1,l1);
    split_bf16(v.z,h2,l2); split_bf16(v.w,h3,l3);
    ((__nv_bfloat162*)hi)[i*2+0] = __nv_bfloat162(h0,h1);
    ((__nv_bfloat162*)hi)[i*2+1] = __nv_bfloat162(h2,h3);
    ((__nv_bfloat162*)lo)[i*2+0] = __nv_bfloat162(l0,l1);
    ((__nv_bfloat162*)lo)[i*2+1] = __nv_bfloat162(l2,l3);
}

// ---------------------------------------------------------------------------
// Prep: transpose + split. W[K][N] fp32 -> Th/Tl[N][K] bf16.
// ---------------------------------------------------------------------------
__global__ void tsplit_kernel(const float* __restrict__ W,
                              __nv_bfloat16* __restrict__ Th,
                              __nv_bfloat16* __restrict__ Tl)
{
    __shared__ float t[32][33];
    const int n0 = blockIdx.x * 32, k0 = blockIdx.y * 32;
    const int tx = threadIdx.x, ty = threadIdx.y;   // (32, 8)
    #pragma unroll
    for (int i = 0; i < 4; i++)
        t[ty + 8*i][tx] = W[(size_t)(k0 + ty + 8*i) * E_ + n0 + tx];
    __syncthreads();
    #pragma unroll
    for (int i = 0; i < 4; i++) {
        const int row = ty + 8*i;
        const float v = t[tx][row];
        __nv_bfloat16 h, l;
        split_bf16(v, h, l);
        Th[(size_t)(n0 + row) * E_ + k0 + tx] = h;
        Tl[(size_t)(n0 + row) * E_ + k0 + tx] = l;
    }
}

// ---------------------------------------------------------------------------
// bf16x3 tensor-core GEMM with ldmatrix + 3-stage cp.async.
// REORDER=true:  write split bf16 hi/lo in [B,H,T,hd] layout (Ch, Cl).
// REORDER=false: write fp32 [M][N] (C).
// ---------------------------------------------------------------------------
#define GS_STRIDE 80
#define GS_TILE   (128*GS_STRIDE)      // 10240 B
#define GS_STAGE  (4*GS_TILE)          // 40960 B
#define GS_SMEM   (3*GS_STAGE)         // 122880 B

template<bool REORDER>
__global__ void __launch_bounds__(256) gemm_bf16x3(
    const __nv_bfloat16* __restrict__ Ah, const __nv_bfloat16* __restrict__ Al,
    const __nv_bfloat16* __restrict__ Th, const __nv_bfloat16* __restrict__ Tl,
    const float* __restrict__ bias, float* __restrict__ C,
    __nv_bfloat16* __restrict__ Ch, __nv_bfloat16* __restrict__ Cl)
{
    extern __shared__ char sm[];
    const uint32_t smb = smem_u32(sm);

    const int tid  = threadIdx.x;
    const int warp = tid >> 5;
    const int lane = tid & 31;
    const int group = lane >> 2;
    const int tidg  = lane & 3;

    const int bn = blockIdx.x, bm = blockIdx.y;
    const int m0 = bm * 128, n0 = bn * 128;
    const int warp_m = warp & 1;
    const int warp_n = warp >> 1;

    const int lrow = (lane & 7) + ((lane >> 3) & 1) * 8;
    const int lkb  = ((lane >> 4) & 1) * 16;

    auto load_stage = [&](int s, int c) {
        const int kb = c * 32;
        const uint32_t st = smb + s * GS_STAGE;
        #pragma unroll
        for (int i = 0; i < 2; i++) {
            const int ch = tid + i * 256;
            const int row = ch >> 2, q = ch & 3;
            const uint32_t d = st + row * GS_STRIDE + q * 16;
            const size_t ga = (size_t)(m0 + row) * E_ + kb + q * 8;
            const size_t gb = (size_t)(n0 + row) * E_ + kb + q * 8;
            cp_async16(d,               Ah + ga);
            cp_async16(d + GS_TILE,     Al + ga);
            cp_async16(d + 2*GS_TILE,   Th + gb);
            cp_async16(d + 3*GS_TILE,   Tl + gb);
        }
        cp_commit();
    };

    float acc[4][4][4];
    #pragma unroll
    for (int i = 0; i < 4; i++)
        #pragma unroll
        for (int j = 0; j < 4; j++)
            #pragma unroll
            for (int r = 0; r < 4; r++) acc[i][j][r] = 0.f;

    const int NC = E_ / 32;
    load_stage(0, 0);
    load_stage(1, 1);
    load_stage(2, 2);

    int s = 0;
    for (int c = 0; c < NC; c++) {
        if (c >= NC - 1)      cp_wait0();
        else if (c >= NC - 2) cp_wait1();
        else                  cp_wait2();
        __syncthreads();

        const uint32_t st = smb + s * GS_STAGE;
        const uint32_t abase = st + (warp_m * 64 + lrow) * GS_STRIDE + lkb;
        const uint32_t bbase = st + 2*GS_TILE + (warp_n * 32 + lrow) * GS_STRIDE + lkb;

        #pragma unroll
        for (int h2 = 0; h2 < 2; h2++) {
            const int ko = h2 * 32;
            uint32_t ah[4][4], al[4][4], bh[2][4], bl[2][4];
            #pragma unroll
            for (int i = 0; i < 4; i++) {
                ldsm_x4(ah[i], abase + i * 16 * GS_STRIDE + ko);
                ldsm_x4(al[i], abase + GS_TILE + i * 16 * GS_STRIDE + ko);
            }
            #pragma unroll
            for (int g = 0; g < 2; g++) {
                ldsm_x4(bh[g], bbase + g * 16 * GS_STRIDE + ko);
                ldsm_x4(bl[g], bbase + GS_TILE + g * 16 * GS_STRIDE + ko);
            }
            #pragma unroll
            for (int i = 0; i < 4; i++)
                #pragma unroll
                for (int j = 0; j < 4; j++)
                    mma_bf16(acc[i][j], ah[i], bh[j>>1][j&1], bh[j>>1][(j&1)+2]);
            #pragma unroll
            for (int i = 0; i < 4; i++)
                #pragma unroll
                for (int j = 0; j < 4; j++)
                    mma_bf16(acc[i][j], ah[i], bl[j>>1][j&1], bl[j>>1][(j&1)+2]);
            #pragma unroll
            for (int i = 0; i < 4; i++)
                #pragma unroll
                for (int j = 0; j < 4; j++)
                    mma_bf16(acc[i][j], al[i], bh[j>>1][j&1], bh[j>>1][(j&1)+2]);
        }
        __syncthreads();
        if (c + 3 < NC) load_stage(s, c + 3);
        s = (s == 2) ? 0 : s + 1;
    }

    #pragma unroll
    for (int i = 0; i < 4; i++) {
        const int rmb = m0 + warp_m * 64 + i * 16 + group;
        #pragma unroll
        for (int j = 0; j < 4; j++) {
            const int cb = n0 + warp_n * 32 + j * 8 + tidg * 2;
            const float bx = bias[cb], by = bias[cb + 1];
            #pragma unroll
            for (int half = 0; half < 2; half++) {
                const int m = rmb + half * 8;
                const float vx = acc[i][j][half * 2 + 0] + bx;
                const float vy = acc[i][j][half * 2 + 1] + by;
                if (REORDER) {
                    const int b = m >> 11;
                    const int t = m & (T_ - 1);
                    const int h = cb >> 6;
                    const int d = cb & (HD_ - 1);
                    const size_t o = (((size_t)(b * H_ + h) * T_) + t) * HD_ + d;
                    __nv_bfloat16 hx, lx, hy, ly;
                    split_bf16(vx, hx, lx);
                    split_bf16(vy, hy, ly);
                    *(uint32_t*)&Ch[o] = pack_bf162(hx, hy);
                    *(uint32_t*)&Cl[o] = pack_bf162(lx, ly);
                } else {
                    float2 v; v.x = vx; v.y = vy;
                    *(float2*)&C[(size_t)m * E_ + cb] = v;
                }
            }
        }
    }
}

// ---------------------------------------------------------------------------
// Tensor-core flash attention (causal), bf16x3 compensated.
// Block = 128 q rows of one (b,h); 8 warps x 16 rows. KV tiles 64, 2 stages.
// Smem tile: 64 rows x 144B (128B data + 16 pad). Stage = Kh,Kl,Vh,Vl.
// ---------------------------------------------------------------------------
#define AT_STRIDE 144
#define AT_TILE   (64*AT_STRIDE)     // 9216
#define AT_STAGE  (4*AT_TILE)        // 36864
#define AT_SMEM   (2*AT_STAGE)       // 73728

__global__ void __launch_bounds__(256) attn_tc(
    const __nv_bfloat16* __restrict__ Qh, const __nv_bfloat16* __restrict__ Ql,
    const __nv_bfloat16* __restrict__ Kh, const __nv_bfloat16* __restrict__ Kl,
    const __nv_bfloat16* __restrict__ Vh, const __nv_bfloat16* __restrict__ Vl,
    __nv_bfloat16* __restrict__ Yh, __nv_bfloat16* __restrict__ Yl)
{
    extern __shared__ char sm[];
    const uint32_t smb = smem_u32(sm);

    const int tid  = threadIdx.x;
    const int warp = tid >> 5;
    const int lane = tid & 31;
    const int g    = lane >> 2;
    const int t4   = lane & 3;

    const int qb = blockIdx.x;
    const int h  = blockIdx.y;
    const int b  = blockIdx.z;
    const int q0 = qb * 128;

    const size_t base = (size_t)(b * H_ + h) * T_ * HD_;
    const __nv_bfloat16* qh = Qh + base + (size_t)q0 * HD_;
    const __nv_bfloat16* ql = Ql + base + (size_t)q0 * HD_;
    const __nv_bfloat16* kh = Kh + base;
    const __nv_bfloat16* kl = Kl + base;
    const __nv_bfloat16* vh = Vh + base;
    const __nv_bfloat16* vl = Vl + base;

    // ldmatrix lane addressing
    const int arow = (lane & 7) + ((lane >> 3) & 1) * 8;   // A & V(trans) row
    const int achk = (lane >> 4) & 1;                      // A & V(trans) chunk
    const int brow = (lane & 7) + ((lane >> 4) & 1) * 8;   // K(B) row
    const int bchk = (lane >> 3) & 1;                      // K(B) chunk

    // ---- load Q (128x64 hi/lo) into stage0 region, pull into fragments ----
    #pragma unroll
    for (int i = 0; i < 4; i++) {
        const int ch = tid + i * 256;            // 0..1023
        const int row = ch >> 3, q = ch & 7;
        const uint32_t d = smb + (row >> 6) * AT_TILE + (row & 63) * AT_STRIDE + q * 16;
        cp_async16(d,               qh + (size_t)row * HD_ + q * 8);
        cp_async16(d + 2*AT_TILE,   ql + (size_t)row * HD_ + q * 8);
    }
    cp_commit(); cp_wait0();
    __syncthreads();

    uint32_t qfh[4][4], qfl[4][4];
    {
        const int wr = warp * 16;
        const uint32_t qbse = smb + (wr >> 6) * AT_TILE + (wr & 63) * AT_STRIDE
                            + arow * AT_STRIDE + achk * 16;
        #pragma unroll
        for (int kc = 0; kc < 4; kc++) {
            ldsm_x4(qfh[kc], qbse + kc * 32);
            ldsm_x4(qfl[kc], qbse + 2*AT_TILE + kc * 32);
        }
    }
    __syncthreads();

    // ---- pipeline over KV tiles ----
    auto load_stage = [&](int s, int kt) {
        const int kv0 = kt * 64;
        const uint32_t st = smb + s * AT_STAGE;
        #pragma unroll
        for (int i = 0; i < 2; i++) {
            const int ch = tid + i * 256;          // 0..511
            const int row = ch >> 3, q = ch & 7;
            const uint32_t d = st + row * AT_STRIDE + q * 16;
            const size_t go = (size_t)(kv0 + row) * HD_ + q * 8;
            cp_async16(d,               kh + go);
            cp_async16(d + AT_TILE,     kl + go);
            cp_async16(d + 2*AT_TILE,   vh + go);
            cp_async16(d + 3*AT_TILE,   vl + go);
        }
        cp_commit();
    };

    float O[8][4];
    #pragma unroll
    for (int j = 0; j < 8; j++)
        #pragma unroll
        for (int r = 0; r < 4; r++) O[j][r] = 0.f;
    float m0 = -1e30f, m1 = -1e30f, l0 = 0.f, l1 = 0.f;

    const int nt = 2 * (qb + 1);
    const int R  = q0 + warp * 16;     // warp's first q row

    load_stage(0, 0);
    if (nt > 1) load_stage(1, 1);

    for (int kt = 0; kt < nt; kt++) {
        const int s = kt & 1;
        const int kv0 = kt * 64;
        if (kt + 1 < nt) cp_wait1(); else cp_wait0();
        __syncthreads();

        if (kv0 <= R + 15) {
            const uint32_t st = smb + s * AT_STAGE;

            // ---- S = Q K^T (bf16x3) ----
            float S[8][4];
            #pragma unroll
            for (int j = 0; j < 8; j++)
                #pragma unroll
                for (int r = 0; r < 4; r++) S[j][r] = 0.f;

            #pragma unroll
            for (int kc = 0; kc < 4; kc++) {
                uint32_t kfh[16], kfl[16];
                #pragma unroll
                for (int np = 0; np < 4; np++) {
                    const uint32_t a = st + (np * 16 + brow) * AT_STRIDE + bchk * 16 + kc * 32;
                    ldsm_x4(&kfh[np * 4], a);
                    ldsm_x4(&kfl[np * 4], a + AT_TILE);
                }
                #pragma unroll
                for (int j = 0; j < 8; j++) {
                    const int ix = (j >> 1) * 4 + (j & 1) * 2;
                    mma_bf16(S[j], qfh[kc], kfh[ix], kfh[ix + 1]);
                }
                #pragma unroll
                for (int j = 0; j < 8; j++) {
                    const int ix = (j >> 1) * 4 + (j & 1) * 2;
                    mma_bf16(S[j], qfh[kc], kfl[ix], kfl[ix + 1]);
                }
                #pragma unroll
                for (int j = 0; j < 8; j++) {
                    const int ix = (j >> 1) * 4 + (j & 1) * 2;
                    mma_bf16(S[j], qfl[kc], kfh[ix], kfh[ix + 1]);
                }
            }

            // scale + causal mask
            const int row0 = R + g, row1 = R + g + 8;
            const bool need_mask = (kv0 + 63 > R);
            #pragma unroll
            for (int j = 0; j < 8; j++) {
                #pragma unroll
                for (int r = 0; r < 4; r++) S[j][r] *= 0.125f;
                if (need_mask) {
                    const int c0 = kv0 + 8 * j + 2 * t4;
                    if (c0     > row0) S[j][0] = -1e30f;
                    if (c0 + 1 > row0) S[j][1] = -1e30f;
                    if (c0     > row1) S[j][2] = -1e30f;
                    if (c0 + 1 > row1) S[j][3] = -1e30f;
                }
            }

            // ---- online softmax (rows g, g+8), quad-shuffle reductions ----
            float mx0 = -1e30f, mx1 = -1e30f;
            #pragma unroll
            for (int j = 0; j < 8; j++) {
                mx0 = fmaxf(mx0, fmaxf(S[j][0], S[j][1]));
                mx1 = fmaxf(mx1, fmaxf(S[j][2], S[j][3]));
            }
            mx0 = fmaxf(mx0, __shfl_xor_sync(0xffffffffu, mx0, 1));
            mx0 = fmaxf(mx0, __shfl_xor_sync(0xffffffffu, mx0, 2));
            mx1 = fmaxf(mx1, __shfl_xor_sync(0xffffffffu, mx1, 1));
            mx1 = fmaxf(mx1, __shfl_xor_sync(0xffffffffu, mx1, 2));

            const float nm0 = fmaxf(m0, mx0);
            const float nm1 = fmaxf(m1, mx1);
            const float cr0 = __expf(m0 - nm0);
            const float cr1 = __expf(m1 - nm1);

            float s0 = 0.f, s1 = 0.f;
            #pragma unroll
            for (int j = 0; j < 8; j++) {
                S[j][0] = __expf(S[j][0] - nm0);
                S[j][1] = __expf(S[j][1] - nm0);
                S[j][2] = __expf(S[j][2] - nm1);
                S[j][3] = __expf(S[j][3] - nm1);
                s0 += S[j][0] + S[j][1];
                s1 += S[j][2] + S[j][3];
            }
            s0 += __shfl_xor_sync(0xffffffffu, s0, 1);
            s0 += __shfl_xor_sync(0xffffffffu, s0, 2);
            s1 += __shfl_xor_sync(0xffffffffu, s1, 1);
            s1 += __shfl_xor_sync(0xffffffffu, s1, 2);

            l0 = l0 * cr0 + s0;  m0 = nm0;
            l1 = l1 * cr1 + s1;  m1 = nm1;

            #pragma unroll
            for (int j = 0; j < 8; j++) {
                O[j][0] *= cr0;  O[j][1] *= cr0;
                O[j][2] *= cr1;  O[j][3] *= cr1;
            }

            // ---- P fragments (hi/lo), C-frag layout == A-frag layout ----
            uint32_t ph[4][4], pl[4][4];
            #pragma unroll
            for (int kc = 0; kc < 4; kc++) {
                __nv_bfloat16 ha, la, hb, lb;
                split_bf16(S[2*kc][0], ha, la);  split_bf16(S[2*kc][1], hb, lb);
                ph[kc][0] = pack_bf162(ha, hb);  pl[kc][0] = pack_bf162(la, lb);
                split_bf16(S[2*kc][2], ha, la);  split_bf16(S[2*kc][3], hb, lb);
                ph[kc][1] = pack_bf162(ha, hb);  pl[kc][1] = pack_bf162(la, lb);
                split_bf16(S[2*kc+1][0], ha, la); split_bf16(S[2*kc+1][1], hb, lb);
                ph[kc][2] = pack_bf162(ha, hb);  pl[kc][2] = pack_bf162(la, lb);
                split_bf16(S[2*kc+1][2], ha, la); split_bf16(S[2*kc+1][3], hb, lb);
                ph[kc][3] = pack_bf162(ha, hb);  pl[kc][3] = pack_bf162(la, lb);
            }

            // ---- O += P V (bf16x3) ----
            #pragma unroll
            for (int kc = 0; kc < 4; kc++) {
                uint32_t vfh[16], vfl[16];
                #pragma unroll
                for (int np = 0; np < 4; np++) {
                    const uint32_t a = st + 2*AT_TILE + (kc * 16 + arow) * AT_STRIDE
                                     + np * 32 + achk * 16;
                    ldsm_x4t(&vfh[np * 4], a);
                    ldsm_x4t(&vfl[np * 4], a + AT_TILE);
                }
                #pragma unroll
                for (int j = 0; j < 8; j++) {
                    const int ix = (j >> 1) * 4 + (j & 1) * 2;
                    mma_bf16(O[j], ph[kc], vfh[ix], vfh[ix + 1]);
                }
                #pragma unroll
                for (int j = 0; j < 8; j++) {
                    const int ix = (j >> 1) * 4 + (j & 1) * 2;
                    mma_bf16(O[j], pl[kc], vfh[ix], vfh[ix + 1]);
                }
                #pragma unroll
                for (int j = 0; j < 8; j++) {
                    const int ix = (j >> 1) * 4 + (j & 1) * 2;
                    mma_bf16(O[j], ph[kc], vfl[ix], vfl[ix + 1]);
                }
            }
        }

        __syncthreads();
        if (kt + 2 < nt) load_stage(s, kt + 2);
    }

    // ---- epilogue: Y[b, q, h*64 + d] split hi/lo ----
    const float inv0 = 1.0f / l0;
    const float inv1 = 1.0f / l1;
    const int row0 = q0 + warp * 16 + g;
    const int row1 = row0 + 8;
    #pragma unroll
    for (int j = 0; j < 8; j++) {
        const int col = h * HD_ + 8 * j + 2 * t4;
        const size_t o0 = (size_t)(b * T_ + row0) * E_ + col;
        const size_t o1 = (size_t)(b * T_ + row1) * E_ + col;
        __nv_bfloat16 ha, la, hb, lb;
        split_bf16(O[j][0] * inv0, ha, la);
        split_bf16(O[j][1] * inv0, hb, lb);
        *(uint32_t*)&Yh[o0] = pack_bf162(ha, hb);
        *(uint32_t*)&Yl[o0] = pack_bf162(la, lb);
        split_bf16(O[j][2] * inv1, ha, la);
        split_bf16(O[j][3] * inv1, hb, lb);
        *(uint32_t*)&Yh[o1] = pack_bf162(ha, hb);
        *(uint32_t*)&Yl[o1] = pack_bf162(la, lb);
    }
}

// ---------------------------------------------------------------------------
extern "C" void kernel_launch(void* const* d_in, const int* in_sizes, int n_in,
                              void* d_out, int out_size)
{
    const float* x  = (const float*)d_in[0];
    const float* Wq = (const float*)d_in[2];
    const float* bq = (const float*)d_in[3];
    const float* Wk = (const float*)d_in[4];
    const float* bk = (const float*)d_in[5];
    const float* Wv = (const float*)d_in[6];
    const float* bv = (const float*)d_in[7];
    const float* Wp = (const float*)d_in[8];
    const float* bp = (const float*)d_in[9];
    float* out = (float*)d_out;

    __nv_bfloat16 *xh, *xl, *yh, *yl, *qh, *ql, *kh, *kl, *vh, *vl;
    __nv_bfloat16 *wqh, *wql, *wkh, *wkl, *wvh, *wvl, *wph, *wpl;
    cudaGetSymbolAddress((void**)&xh, g_xh);  cudaGetSymbolAddress((void**)&xl, g_xl);
    cudaGetSymbolAddress((void**)&yh, g_yh);  cudaGetSymbolAddress((void**)&yl, g_yl);
    cudaGetSymbolAddress((void**)&qh, g_qh);  cudaGetSymbolAddress((void**)&ql, g_ql);
    cudaGetSymbolAddress((void**)&kh, g_kh);  cudaGetSymbolAddress((void**)&kl, g_kl);
    cudaGetSymbolAddress((void**)&vh, g_vh);  cudaGetSymbolAddress((void**)&vl, g_vl);
    cudaGetSymbolAddress((void**)&wqh, g_wqh);  cudaGetSymbolAddress((void**)&wql, g_wql);
    cudaGetSymbolAddress((void**)&wkh, g_wkh);  cudaGetSymbolAddress((void**)&wkl, g_wkl);
    cudaGetSymbolAddress((void**)&wvh, g_wvh);  cudaGetSymbolAddress((void**)&wvl, g_wvl);
    cudaGetSymbolAddress((void**)&wph, g_wph);  cudaGetSymbolAddress((void**)&wpl, g_wpl);

    cudaFuncSetAttribute(gemm_bf16x3<true>,  cudaFuncAttributeMaxDynamicSharedMemorySize, GS_SMEM);
    cudaFuncSetAttribute(gemm_bf16x3<false>, cudaFuncAttributeMaxDynamicSharedMemorySize, GS_SMEM);
    cudaFuncSetAttribute(attn_tc, cudaFuncAttributeMaxDynamicSharedMemorySize, AT_SMEM);

    // Prep: split x, transpose+split weights
    split_kernel<<<(M_*E_/4 + 255)/256, 256>>>(x, xh, xl, M_*E_/4);
    dim3 tgrid(E_/32, E_/32), tblk(32, 8);
    tsplit_kernel<<<tgrid, tblk>>>(Wq, wqh, wql);
    tsplit_kernel<<<tgrid, tblk>>>(Wk, wkh, wkl);
    tsplit_kernel<<<tgrid, tblk>>>(Wv, wvh, wvl);
    tsplit_kernel<<<tgrid, tblk>>>(Wp, wph, wpl);

    dim3 gemm_grid(E_ / 128, M_ / 128);  // (8, 64)
    gemm_bf16x3<true><<<gemm_grid, 256, GS_SMEM>>>(xh, xl, wqh, wql, bq, nullptr, qh, ql);
    gemm_bf16x3<true><<<gemm_grid, 256, GS_SMEM>>>(xh, xl, wkh, wkl, bk, nullptr, kh, kl);
    gemm_bf16x3<true><<<gemm_grid, 256, GS_SMEM>>>(xh, xl, wvh, wvl, bv, nullptr, vh, vl);

    dim3 attn_grid(T_ / 128, H_, B_);    // (16, 16, 4)
    attn_tc<<<attn_grid, 256, AT_SMEM>>>(qh, ql, kh, kl, vh, vl, yh, yl);

    gemm_bf16x3<false><<<gemm_grid, 256, GS_SMEM>>>(yh, yl, wph, wpl, bp, out, nullptr, nullptr);
}